// round 14
// baseline (speedup 1.0000x reference)
#include <cuda_runtime.h>

// Problem constants
#define S_LEN   512
#define HDIM    1024
#define BATCH   64
#define IDIM    1024
#define M_TOT   (BATCH * S_LEN)          // 32768
#define OUT_TAIL (BATCH * S_LEN * HDIM)  // offset of h_last region in d_out

typedef unsigned long long u64;

// ---- packed f32x2 helpers (SASS FFMA2 path, PTX-only) ----
__device__ __forceinline__ u64 pack2(float lo, float hi) {
    u64 r;
    asm("mov.b64 %0, {%1, %2};" : "=l"(r) : "f"(lo), "f"(hi));
    return r;
}
__device__ __forceinline__ void unpack2(float& lo, float& hi, u64 v) {
    asm("mov.b64 {%0, %1}, %2;" : "=f"(lo), "=f"(hi) : "l"(v));
}
__device__ __forceinline__ void fma2(u64& d, u64 a, u64 b) {
    asm("fma.rn.f32x2 %0, %1, %2, %0;" : "+l"(d) : "l"(a), "l"(b));
}
__device__ __forceinline__ uint4 ldv4(const unsigned* p) {
    uint4 v;
    asm volatile("ld.volatile.global.v4.u32 {%0,%1,%2,%3}, [%4];"
        : "=r"(v.x), "=r"(v.y), "=r"(v.z), "=r"(v.w) : "l"(p) : "memory");
    return v;
}

// ====================================================================
// Kernel 1: input projection GEMM with f32x2 accumulation (unchanged)
// ====================================================================
__global__ void __launch_bounds__(256) xproj_kernel(
    const float* __restrict__ A,
    const float* __restrict__ W,
    const float* __restrict__ bih,
    const float* __restrict__ bhh,
    float* __restrict__ C)
{
    __shared__ float As[16][132];
    __shared__ float Bs[16][132];

    const int tid = threadIdx.x;
    const int tx  = tid & 15;
    const int ty  = tid >> 4;
    const int m0  = blockIdx.y * 128;
    const int n0  = blockIdx.x * 128;

    u64 acc2[8][4];
#pragma unroll
    for (int i = 0; i < 8; i++)
#pragma unroll
        for (int p = 0; p < 4; p++) acc2[i][p] = 0ull;

    const float4* A4 = (const float4*)A;
    const float4* W4 = (const float4*)W;

    for (int k0 = 0; k0 < IDIM; k0 += 16) {
        const int kq = k0 >> 2;
#pragma unroll
        for (int q = 0; q < 2; q++) {
            int f  = q * 256 + tid;
            int r  = f >> 2;
            int c4 = f & 3;
            float4 av = A4[(size_t)(m0 + r) * 256 + kq + c4];
            As[c4 * 4 + 0][r] = av.x;
            As[c4 * 4 + 1][r] = av.y;
            As[c4 * 4 + 2][r] = av.z;
            As[c4 * 4 + 3][r] = av.w;
            float4 bv = W4[(size_t)(n0 + r) * 256 + kq + c4];
            Bs[c4 * 4 + 0][r] = bv.x;
            Bs[c4 * 4 + 1][r] = bv.y;
            Bs[c4 * 4 + 2][r] = bv.z;
            Bs[c4 * 4 + 3][r] = bv.w;
        }
        __syncthreads();

#pragma unroll
        for (int kk = 0; kk < 16; kk++) {
            float ra[8];
            *(float4*)&ra[0] = *(const float4*)&As[kk][ty * 4];
            *(float4*)&ra[4] = *(const float4*)&As[kk][64 + ty * 4];
            ulonglong2 rb0 = *(const ulonglong2*)&Bs[kk][tx * 4];
            ulonglong2 rb1 = *(const ulonglong2*)&Bs[kk][64 + tx * 4];
#pragma unroll
            for (int i = 0; i < 8; i++) {
                u64 rap = pack2(ra[i], ra[i]);
                fma2(acc2[i][0], rap, rb0.x);
                fma2(acc2[i][1], rap, rb0.y);
                fma2(acc2[i][2], rap, rb1.x);
                fma2(acc2[i][3], rap, rb1.y);
            }
        }
        __syncthreads();
    }

    float bsum[8];
#pragma unroll
    for (int j = 0; j < 8; j++) {
        int n = n0 + ((j < 4) ? (tx * 4 + j) : (64 + tx * 4 + (j - 4)));
        bsum[j] = bih[n] + bhh[n];
    }
#pragma unroll
    for (int i = 0; i < 8; i++) {
        int m = m0 + ((i < 4) ? (ty * 4 + i) : (64 + ty * 4 + (i - 4)));
        float c[8];
        unpack2(c[0], c[1], acc2[i][0]);
        unpack2(c[2], c[3], acc2[i][1]);
        unpack2(c[4], c[5], acc2[i][2]);
        unpack2(c[6], c[7], acc2[i][3]);
        float4 v0, v1;
        v0.x = c[0] + bsum[0]; v0.y = c[1] + bsum[1];
        v0.z = c[2] + bsum[2]; v0.w = c[3] + bsum[3];
        v1.x = c[4] + bsum[4]; v1.y = c[5] + bsum[5];
        v1.z = c[6] + bsum[6]; v1.w = c[7] + bsum[7];
        *(float4*)&C[(size_t)m * HDIM + n0 + tx * 4]      = v0;
        *(float4*)&C[(size_t)m * HDIM + n0 + 64 + tx * 4] = v1;
    }
}

// ====================================================================
// Kernel 2: persistent recurrence, v13 (= R11 core + decentralized
//   producer->consumer flags instead of a group barrier).
//   128 CTAs = 4 groups x 32 CTAs, 256 threads (8 warps).
//   Warp w consumes h cols [w*128,+128) = tiles of CTAs 4w..4w+3 only:
//   it polls exactly those 4 write-once flags (one 16B volatile load).
//   Flags zeroed at kernel end after a single count-reset group barrier
//   (all state returns to 0 -> graph-replay safe).
// ====================================================================
#define WSTR 1028                     // hsm/Wsm row stride (floats)
#define RSTR 40                       // partials: conflict-free pattern
#define RED_WSZ (16 * RSTR)           // 640 floats per warp
#define SM_H   (32 * WSTR)
#define SM_RED (48 * WSTR)
#define REC_SMEM_FLOATS (48 * WSTR + 8 * RED_WSZ)
#define REC_SMEM_BYTES  (REC_SMEM_FLOATS * 4)

__device__ __align__(128) unsigned g_flag[4][S_LEN][32];  // write-once per run
__device__ unsigned g_cnt[4];                             // cleanup barrier

__global__ void __launch_bounds__(256, 1) rec_kernel(
    const float* __restrict__ h0,
    const float* __restrict__ Whh,
    float* out)
{
    extern __shared__ float sm[];
    float* Wsm = sm;              // [32][WSTR]
    float* hsm = sm + SM_H;       // [16][WSTR] (columns warp-disjoint)
    float* red = sm + SM_RED;     // [8][16*RSTR]

    const int cta = blockIdx.x;
    const int grp = cta >> 5;        // 0..3 batch group
    const int gc  = cta & 31;        // 0..31 within group
    const int j0  = gc * 32;
    const int b0g = grp * 16;
    const int tid = threadIdx.x;
    const int w   = tid >> 5;        // warp: owns K chunk [w*128, +128)
    const int l   = tid & 31;
    const int jj  = l & 7;           // j rows: jj, jj+8, jj+16, jj+24
    const int bb  = l >> 3;          // b rows: bb, bb+4, bb+8, bb+12

    // ---- load W_hh rows [j0, j0+32) into SMEM once ----
    {
        const float4* W4 = (const float4*)Whh;
        for (int i = tid; i < 32 * 256; i += 256) {
            int r = i >> 8, c = i & 255;
            *(float4*)&Wsm[r * WSTR + c * 4] = W4[(size_t)(j0 + r) * 256 + c];
        }
    }
    __syncthreads();

    // dot-loop base pointers (k-chunk offset w*128 floats)
    const ulonglong2* wp[4];
    const ulonglong2* hp[4];
#pragma unroll
    for (int i = 0; i < 4; i++)
        wp[i] = (const ulonglong2*)(Wsm + (jj + 8 * i) * WSTR + w * 128);
#pragma unroll
    for (int m = 0; m < 4; m++)
        hp[m] = (const ulonglong2*)(hsm + (bb + 4 * m) * WSTR + w * 128);

    // reduce-phase mapping: thread -> (b, j-pair)
    const int rb = tid >> 4;          // 0..15
    const int rj = (tid & 15) * 2;    // 0..30 even
    const int bglob_r = b0g + rb;
    const int jglob_r = j0 + rj;
    const size_t obase = (size_t)bglob_r * S_LEN * HDIM + jglob_r;

    // xp for step 0 (prefetched; this thread is sole writer of this addr)
    float2 xv = *(const float2*)&out[obase];

    for (int t = 0; t < S_LEN; t++) {
        // ---- wait for this warp's 4 producers (t>0), then stage ----
        if (t > 0) {
            if (l == 0) {
                const unsigned* fp = &g_flag[grp][t - 1][4 * w];
                uint4 f;
                do { f = ldv4(fp); } while ((f.x & f.y & f.z & f.w) == 0u);
            }
            __syncwarp();
            __threadfence();   // acquire before reading producers' h
        }

        const float4* H4 = (t == 0)
            ? (const float4*)h0
            : (const float4*)(out + (size_t)(t - 1) * HDIM);
        const size_t rstride = (t == 0) ? 256u : (size_t)S_LEN * 256u;

        float4 va[8], vb[8];
#pragma unroll
        for (int q = 0; q < 8; q++) {          // chunk A loads
            int f = q * 32 + l, r = f >> 4, c4 = f & 15;
            va[q] = __ldcv(&H4[(size_t)(b0g + r) * rstride + w * 32 + c4]);
        }
#pragma unroll
        for (int q = 0; q < 8; q++) {          // chunk B loads (in flight)
            int f = q * 32 + l, r = f >> 4, c4 = f & 15;
            vb[q] = __ldcv(&H4[(size_t)(b0g + r) * rstride + w * 32 + 16 + c4]);
        }
#pragma unroll
        for (int q = 0; q < 8; q++) {          // STS chunk A
            int f = q * 32 + l, r = f >> 4, c4 = f & 15;
            *(float4*)&hsm[r * WSTR + (w * 32 + c4) * 4] = va[q];
        }
        __syncwarp();

        // ---- dot on chunk A (kq 0..15), double-buffered LDS ----
        u64 acc[4][4];
#pragma unroll
        for (int m = 0; m < 4; m++)
#pragma unroll
            for (int i = 0; i < 4; i++) acc[m][i] = 0ull;

        ulonglong2 wv[2][4], hv[2][4];
#pragma unroll
        for (int i = 0; i < 4; i++) wv[0][i] = wp[i][0];
#pragma unroll
        for (int m = 0; m < 4; m++) hv[0][m] = hp[m][0];

#pragma unroll
        for (int kq = 0; kq < 16; kq++) {
            const int cur = kq & 1;
            const int nxt = cur ^ 1;
            if (kq < 15) {
#pragma unroll
                for (int i = 0; i < 4; i++) wv[nxt][i] = wp[i][kq + 1];
#pragma unroll
                for (int m = 0; m < 4; m++) hv[nxt][m] = hp[m][kq + 1];
            }
#pragma unroll
            for (int m = 0; m < 4; m++)
#pragma unroll
                for (int i = 0; i < 4; i++) {
                    fma2(acc[m][i], wv[cur][i].x, hv[cur][m].x);
                    fma2(acc[m][i], wv[cur][i].y, hv[cur][m].y);
                }
        }

        // ---- STS chunk B, then dot chunk B (kq 16..31) ----
#pragma unroll
        for (int q = 0; q < 8; q++) {
            int f = q * 32 + l, r = f >> 4, c4 = f & 15;
            *(float4*)&hsm[r * WSTR + (w * 32 + 16 + c4) * 4] = vb[q];
        }
        __syncwarp();

#pragma unroll
        for (int i = 0; i < 4; i++) wv[0][i] = wp[i][16];
#pragma unroll
        for (int m = 0; m < 4; m++) hv[0][m] = hp[m][16];

#pragma unroll
        for (int kq = 16; kq < 32; kq++) {
            const int cur = kq & 1;
            const int nxt = cur ^ 1;
            if (kq < 31) {
#pragma unroll
                for (int i = 0; i < 4; i++) wv[nxt][i] = wp[i][kq + 1];
#pragma unroll
                for (int m = 0; m < 4; m++) hv[nxt][m] = hp[m][kq + 1];
            }
#pragma unroll
            for (int m = 0; m < 4; m++)
#pragma unroll
                for (int i = 0; i < 4; i++) {
                    fma2(acc[m][i], wv[cur][i].x, hv[cur][m].x);
                    fma2(acc[m][i], wv[cur][i].y, hv[cur][m].y);
                }
        }

        // ---- store partials (conflict-free with RSTR=40) ----
        float* rw = red + w * RED_WSZ;
#pragma unroll
        for (int m = 0; m < 4; m++)
#pragma unroll
            for (int i = 0; i < 4; i++) {
                float lo, hi;
                unpack2(lo, hi, acc[m][i]);
                rw[(bb + 4 * m) * RSTR + (jj + 8 * i)] = lo + hi;
            }
        __syncthreads();

        // ---- reduce 8 warps + xp + relu; prefetch next xp; store h ----
        float s0 = xv.x, s1 = xv.y;
#pragma unroll
        for (int ww = 0; ww < 8; ww++) {
            float2 p = *(const float2*)&red[ww * RED_WSZ + rb * RSTR + rj];
            s0 += p.x;
            s1 += p.y;
        }
        // prefetch xp for t+1 (same (b,j), next t; sole writer is this
        // thread at t+1; t=511 reads a stable/unused in-bounds word)
        float2 xv_next = *(const float2*)&out[obase + (size_t)(t + 1) * HDIM];

        float2 hv2 = make_float2(fmaxf(s0 + 0.0f, 0.0f), fmaxf(s1, 0.0f));
        *(float2*)&out[obase + (size_t)t * HDIM] = hv2;
        if (t == S_LEN - 1) {
            *(float2*)&out[OUT_TAIL + (size_t)bglob_r * HDIM + jglob_r] = hv2;
        }
        __syncthreads();    // all h stores done + red[] safe for reuse

        // ---- publish: non-blocking write-once flag ----
        if (tid == 0) {
            __threadfence();
            *((volatile unsigned*)&g_flag[grp][t][gc]) = 1u;
        }
        xv = xv_next;
    }

    // ---- end: one count-reset group barrier, then zero own flags ----
    if (tid == 0) {
        unsigned old = atomicAdd(&g_cnt[grp], 1u);
        if (old == 31u) {
            atomicExch(&g_cnt[grp], 0u);
        } else {
            while (*((volatile unsigned*)&g_cnt[grp]) != 0u) { }
        }
    }
    __syncthreads();
    for (int tt = tid; tt < S_LEN; tt += 256)
        g_flag[grp][tt][gc] = 0u;
}

// ====================================================================
// Launch
// ====================================================================
extern "C" void kernel_launch(void* const* d_in, const int* in_sizes, int n_in,
                              void* d_out, int out_size)
{
    const float* inputs = (const float*)d_in[0];   // [64,512,1024]
    const float* h0     = (const float*)d_in[1];   // [1,64,1024]
    const float* wih    = (const float*)d_in[2];   // [1024,1024]
    const float* whh    = (const float*)d_in[3];   // [1024,1024]
    const float* bih    = (const float*)d_in[4];   // [1024]
    const float* bhh    = (const float*)d_in[5];   // [1024]
    float* out = (float*)d_out;

    dim3 g1(HDIM / 128, M_TOT / 128);   // (8, 256)
    xproj_kernel<<<g1, 256>>>(inputs, wih, bih, bhh, out);

    cudaFuncSetAttribute(rec_kernel, cudaFuncAttributeMaxDynamicSharedMemorySize,
                         REC_SMEM_BYTES);
    rec_kernel<<<128, 256, REC_SMEM_BYTES>>>(h0, whh, out);
}

// round 16
// speedup vs baseline: 1.3632x; 1.3632x over previous
#include <cuda_runtime.h>

// Problem constants
#define S_LEN   512
#define HDIM    1024
#define BATCH   64
#define IDIM    1024
#define M_TOT   (BATCH * S_LEN)          // 32768
#define OUT_TAIL (BATCH * S_LEN * HDIM)  // offset of h_last region in d_out

typedef unsigned long long u64;

// ---- packed f32x2 helpers (SASS FFMA2 path, PTX-only) ----
__device__ __forceinline__ u64 pack2(float lo, float hi) {
    u64 r;
    asm("mov.b64 %0, {%1, %2};" : "=l"(r) : "f"(lo), "f"(hi));
    return r;
}
__device__ __forceinline__ void unpack2(float& lo, float& hi, u64 v) {
    asm("mov.b64 {%0, %1}, %2;" : "=f"(lo), "=f"(hi) : "l"(v));
}
__device__ __forceinline__ void fma2(u64& d, u64 a, u64 b) {
    asm("fma.rn.f32x2 %0, %1, %2, %0;" : "+l"(d) : "l"(a), "l"(b));
}

// ====================================================================
// Kernel 1: input projection GEMM with f32x2 accumulation (unchanged)
// ====================================================================
__global__ void __launch_bounds__(256) xproj_kernel(
    const float* __restrict__ A,
    const float* __restrict__ W,
    const float* __restrict__ bih,
    const float* __restrict__ bhh,
    float* __restrict__ C)
{
    __shared__ float As[16][132];
    __shared__ float Bs[16][132];

    const int tid = threadIdx.x;
    const int tx  = tid & 15;
    const int ty  = tid >> 4;
    const int m0  = blockIdx.y * 128;
    const int n0  = blockIdx.x * 128;

    u64 acc2[8][4];
#pragma unroll
    for (int i = 0; i < 8; i++)
#pragma unroll
        for (int p = 0; p < 4; p++) acc2[i][p] = 0ull;

    const float4* A4 = (const float4*)A;
    const float4* W4 = (const float4*)W;

    for (int k0 = 0; k0 < IDIM; k0 += 16) {
        const int kq = k0 >> 2;
#pragma unroll
        for (int q = 0; q < 2; q++) {
            int f  = q * 256 + tid;
            int r  = f >> 2;
            int c4 = f & 3;
            float4 av = A4[(size_t)(m0 + r) * 256 + kq + c4];
            As[c4 * 4 + 0][r] = av.x;
            As[c4 * 4 + 1][r] = av.y;
            As[c4 * 4 + 2][r] = av.z;
            As[c4 * 4 + 3][r] = av.w;
            float4 bv = W4[(size_t)(n0 + r) * 256 + kq + c4];
            Bs[c4 * 4 + 0][r] = bv.x;
            Bs[c4 * 4 + 1][r] = bv.y;
            Bs[c4 * 4 + 2][r] = bv.z;
            Bs[c4 * 4 + 3][r] = bv.w;
        }
        __syncthreads();

#pragma unroll
        for (int kk = 0; kk < 16; kk++) {
            float ra[8];
            *(float4*)&ra[0] = *(const float4*)&As[kk][ty * 4];
            *(float4*)&ra[4] = *(const float4*)&As[kk][64 + ty * 4];
            ulonglong2 rb0 = *(const ulonglong2*)&Bs[kk][tx * 4];
            ulonglong2 rb1 = *(const ulonglong2*)&Bs[kk][64 + tx * 4];
#pragma unroll
            for (int i = 0; i < 8; i++) {
                u64 rap = pack2(ra[i], ra[i]);
                fma2(acc2[i][0], rap, rb0.x);
                fma2(acc2[i][1], rap, rb0.y);
                fma2(acc2[i][2], rap, rb1.x);
                fma2(acc2[i][3], rap, rb1.y);
            }
        }
        __syncthreads();
    }

    float bsum[8];
#pragma unroll
    for (int j = 0; j < 8; j++) {
        int n = n0 + ((j < 4) ? (tx * 4 + j) : (64 + tx * 4 + (j - 4)));
        bsum[j] = bih[n] + bhh[n];
    }
#pragma unroll
    for (int i = 0; i < 8; i++) {
        int m = m0 + ((i < 4) ? (ty * 4 + i) : (64 + ty * 4 + (i - 4)));
        float c[8];
        unpack2(c[0], c[1], acc2[i][0]);
        unpack2(c[2], c[3], acc2[i][1]);
        unpack2(c[4], c[5], acc2[i][2]);
        unpack2(c[6], c[7], acc2[i][3]);
        float4 v0, v1;
        v0.x = c[0] + bsum[0]; v0.y = c[1] + bsum[1];
        v0.z = c[2] + bsum[2]; v0.w = c[3] + bsum[3];
        v1.x = c[4] + bsum[4]; v1.y = c[5] + bsum[5];
        v1.z = c[6] + bsum[6]; v1.w = c[7] + bsum[7];
        *(float4*)&C[(size_t)m * HDIM + n0 + tx * 4]      = v0;
        *(float4*)&C[(size_t)m * HDIM + n0 + 64 + tx * 4] = v1;
    }
}

// ====================================================================
// Kernel 2: persistent recurrence, v15 (= R11 best + monotonic REDG
//   barrier with MORALLY-STRONG (ld.volatile) polling).
//   128 CTAs = 4 groups x 32 CTAs, 256 threads (8 warps).
//   Warp w owns K-chunk [w*128,+128): warp-private pipelined staging,
//   double-buffered dot, conflict-free partials, coalesced reduce.
// ====================================================================
#define WSTR 1028                     // hsm/Wsm row stride (floats)
#define RSTR 40                       // partials: conflict-free pattern
#define RED_WSZ (16 * RSTR)           // 640 floats per warp
#define SM_H   (32 * WSTR)
#define SM_RED (48 * WSTR)
#define REC_SMEM_FLOATS (48 * WSTR + 8 * RED_WSZ)
#define REC_SMEM_BYTES  (REC_SMEM_FLOATS * 4)

__device__ unsigned g_arr[4];   // monotonic arrival counters (0 at start/end)
__device__ unsigned g_dep[4];   // departure counters for end-of-run reset

__global__ void __launch_bounds__(256, 1) rec_kernel(
    const float* __restrict__ h0,
    const float* __restrict__ Whh,
    float* out)
{
    extern __shared__ float sm[];
    float* Wsm = sm;              // [32][WSTR]
    float* hsm = sm + SM_H;       // [16][WSTR] (columns warp-disjoint)
    float* red = sm + SM_RED;     // [8][16*RSTR]

    const int cta = blockIdx.x;
    const int grp = cta >> 5;        // 0..3 batch group
    const int gc  = cta & 31;        // 0..31 within group
    const int j0  = gc * 32;
    const int b0g = grp * 16;
    const int tid = threadIdx.x;
    const int w   = tid >> 5;        // warp: owns K chunk [w*128, +128)
    const int l   = tid & 31;
    const int jj  = l & 7;           // j rows: jj, jj+8, jj+16, jj+24
    const int bb  = l >> 3;          // b rows: bb, bb+4, bb+8, bb+12

    // ---- load W_hh rows [j0, j0+32) into SMEM once ----
    {
        const float4* W4 = (const float4*)Whh;
        for (int i = tid; i < 32 * 256; i += 256) {
            int r = i >> 8, c = i & 255;
            *(float4*)&Wsm[r * WSTR + c * 4] = W4[(size_t)(j0 + r) * 256 + c];
        }
    }
    __syncthreads();

    // dot-loop base pointers (k-chunk offset w*128 floats)
    const ulonglong2* wp[4];
    const ulonglong2* hp[4];
#pragma unroll
    for (int i = 0; i < 4; i++)
        wp[i] = (const ulonglong2*)(Wsm + (jj + 8 * i) * WSTR + w * 128);
#pragma unroll
    for (int m = 0; m < 4; m++)
        hp[m] = (const ulonglong2*)(hsm + (bb + 4 * m) * WSTR + w * 128);

    // reduce-phase mapping: thread -> (b, j-pair)
    const int rb = tid >> 4;          // 0..15
    const int rj = (tid & 15) * 2;    // 0..30 even
    const int bglob_r = b0g + rb;
    const int jglob_r = j0 + rj;

    for (int t = 0; t < S_LEN; t++) {
        // ---- xp prefetch into registers (addr written only by this thread) ----
        const size_t oxp = ((size_t)bglob_r * S_LEN + t) * HDIM + jglob_r;
        float2 xv = *(const float2*)&out[oxp];

        // ---- warp-private stage of this warp's k-slice (16 rows x 32 f4) ----
        const float4* H4 = (t == 0)
            ? (const float4*)h0
            : (const float4*)(out + (size_t)(t - 1) * HDIM);
        const size_t rstride = (t == 0) ? 256u : (size_t)S_LEN * 256u;

        float4 va[8], vb[8];
#pragma unroll
        for (int q = 0; q < 8; q++) {          // chunk A loads
            int f = q * 32 + l, r = f >> 4, c4 = f & 15;
            va[q] = __ldcv(&H4[(size_t)(b0g + r) * rstride + w * 32 + c4]);
        }
#pragma unroll
        for (int q = 0; q < 8; q++) {          // chunk B loads (in flight)
            int f = q * 32 + l, r = f >> 4, c4 = f & 15;
            vb[q] = __ldcv(&H4[(size_t)(b0g + r) * rstride + w * 32 + 16 + c4]);
        }
#pragma unroll
        for (int q = 0; q < 8; q++) {          // STS chunk A
            int f = q * 32 + l, r = f >> 4, c4 = f & 15;
            *(float4*)&hsm[r * WSTR + (w * 32 + c4) * 4] = va[q];
        }
        __syncwarp();

        // ---- dot on chunk A (kq 0..15), double-buffered LDS ----
        u64 acc[4][4];
#pragma unroll
        for (int m = 0; m < 4; m++)
#pragma unroll
            for (int i = 0; i < 4; i++) acc[m][i] = 0ull;

        ulonglong2 wv[2][4], hv[2][4];
#pragma unroll
        for (int i = 0; i < 4; i++) wv[0][i] = wp[i][0];
#pragma unroll
        for (int m = 0; m < 4; m++) hv[0][m] = hp[m][0];

#pragma unroll
        for (int kq = 0; kq < 16; kq++) {
            const int cur = kq & 1;
            const int nxt = cur ^ 1;
            if (kq < 15) {
#pragma unroll
                for (int i = 0; i < 4; i++) wv[nxt][i] = wp[i][kq + 1];
#pragma unroll
                for (int m = 0; m < 4; m++) hv[nxt][m] = hp[m][kq + 1];
            }
#pragma unroll
            for (int m = 0; m < 4; m++)
#pragma unroll
                for (int i = 0; i < 4; i++) {
                    fma2(acc[m][i], wv[cur][i].x, hv[cur][m].x);
                    fma2(acc[m][i], wv[cur][i].y, hv[cur][m].y);
                }
        }

        // ---- STS chunk B, then dot chunk B (kq 16..31) ----
#pragma unroll
        for (int q = 0; q < 8; q++) {
            int f = q * 32 + l, r = f >> 4, c4 = f & 15;
            *(float4*)&hsm[r * WSTR + (w * 32 + 16 + c4) * 4] = vb[q];
        }
        __syncwarp();

#pragma unroll
        for (int i = 0; i < 4; i++) wv[0][i] = wp[i][16];
#pragma unroll
        for (int m = 0; m < 4; m++) hv[0][m] = hp[m][16];

#pragma unroll
        for (int kq = 16; kq < 32; kq++) {
            const int cur = kq & 1;
            const int nxt = cur ^ 1;
            if (kq < 31) {
#pragma unroll
                for (int i = 0; i < 4; i++) wv[nxt][i] = wp[i][kq + 1];
#pragma unroll
                for (int m = 0; m < 4; m++) hv[nxt][m] = hp[m][kq + 1];
            }
#pragma unroll
            for (int m = 0; m < 4; m++)
#pragma unroll
                for (int i = 0; i < 4; i++) {
                    fma2(acc[m][i], wv[cur][i].x, hv[cur][m].x);
                    fma2(acc[m][i], wv[cur][i].y, hv[cur][m].y);
                }
        }

        // ---- store partials (conflict-free with RSTR=40) ----
        float* rw = red + w * RED_WSZ;
#pragma unroll
        for (int m = 0; m < 4; m++)
#pragma unroll
            for (int i = 0; i < 4; i++) {
                float lo, hi;
                unpack2(lo, hi, acc[m][i]);
                rw[(bb + 4 * m) * RSTR + (jj + 8 * i)] = lo + hi;
            }
        __syncthreads();

        // ---- reduce 8 warps + xp + relu; store 2 outputs/thread ----
        float s0 = xv.x, s1 = xv.y;
#pragma unroll
        for (int ww = 0; ww < 8; ww++) {
            float2 p = *(const float2*)&red[ww * RED_WSZ + rb * RSTR + rj];
            s0 += p.x;
            s1 += p.y;
        }
        float2 hv2 = make_float2(fmaxf(s0, 0.0f), fmaxf(s1, 0.0f));
        *(float2*)&out[oxp] = hv2;
        if (t == S_LEN - 1) {
            *(float2*)&out[OUT_TAIL + (size_t)bglob_r * HDIM + jglob_r] = hv2;
        }

        // ---- monotonic REDG barrier; poll is ld.volatile (morally strong) ----
        __syncthreads();
        if (tid == 0) {
            __threadfence();                    // publish h_t
            atomicAdd(&g_arr[grp], 1u);         // return unused -> REDG
            const unsigned want = 32u * (unsigned)(t + 1);
            while (*((volatile unsigned*)&g_arr[grp]) < want) { }
            __threadfence();                    // acquire
        }
        __syncthreads();
    }

    // ---- end of run: departure count, then last observer resets to 0 ----
    if (tid == 0) {
        atomicAdd(&g_dep[grp], 1u);             // REDG (after final poll exit)
        if (gc == 0) {
            while (*((volatile unsigned*)&g_dep[grp]) < 32u) { }
            *((volatile unsigned*)&g_arr[grp]) = 0u;  // all CTAs past their
            *((volatile unsigned*)&g_dep[grp]) = 0u;  // last g_arr poll now
            __threadfence();
        }
    }
}

// ====================================================================
// Launch
// ====================================================================
extern "C" void kernel_launch(void* const* d_in, const int* in_sizes, int n_in,
                              void* d_out, int out_size)
{
    const float* inputs = (const float*)d_in[0];   // [64,512,1024]
    const float* h0     = (const float*)d_in[1];   // [1,64,1024]
    const float* wih    = (const float*)d_in[2];   // [1024,1024]
    const float* whh    = (const float*)d_in[3];   // [1024,1024]
    const float* bih    = (const float*)d_in[4];   // [1024]
    const float* bhh    = (const float*)d_in[5];   // [1024]
    float* out = (float*)d_out;

    dim3 g1(HDIM / 128, M_TOT / 128);   // (8, 256)
    xproj_kernel<<<g1, 256>>>(inputs, wih, bih, bhh, out);

    cudaFuncSetAttribute(rec_kernel, cudaFuncAttributeMaxDynamicSharedMemorySize,
                         REC_SMEM_BYTES);
    rec_kernel<<<128, 256, REC_SMEM_BYTES>>>(h0, whh, out);
}